// round 2
// baseline (speedup 1.0000x reference)
#include <cuda_runtime.h>
#include <math.h>

#define N_NODES 50000
#define N_EDGES 800000
#define E_TOT   850000          // + self loops
#define C       64
#define H       4
#define NC      (N_NODES * C)   // 3,200,000
#define NH      (N_NODES * H)   // 200,000

// ---- scratch layout (floats) ----
#define OFF_XH    0
#define SZ_XH     (N_NODES * H * C)        // 12,800,000
#define OFF_ALS   (OFF_XH + SZ_XH)
#define OFF_ALD   (OFF_ALS + NH)
#define OFF_MAX   (OFF_ALD + NH)
#define OFF_DEN   (OFF_MAX + NH)
#define OFF_E     (OFF_DEN + NH)
#define SZ_E      (E_TOT * H)              // 3,400,000
#define OFF_ACC   (OFF_E + SZ_E)
#define OFF_H1    (OFF_ACC + NC)
#define OFF_STATS (OFF_H1 + NC)
#define SCRATCH_TOTAL (OFF_STATS + 128)

__device__ __align__(16) float g_scratch[SCRATCH_TOTAL];
__device__ int g_is64;

__device__ __forceinline__ float lrelu(float x) { return x > 0.f ? x : 0.2f * x; }

// float atomic max via int/uint trick (works for mixed signs, init = -inf)
__device__ __forceinline__ void atomicMaxF(float* addr, float v) {
    if (v >= 0.f) atomicMax((int*)addr, __float_as_int(v));
    else          atomicMin((unsigned int*)addr, __float_as_uint(v));
}

__device__ __forceinline__ void edge_endpoints(const void* ei, int e, int& s, int& d) {
    if (e < N_EDGES) {
        if (g_is64) {
            const long long* p = (const long long*)ei;
            s = (int)p[e]; d = (int)p[N_EDGES + e];
        } else {
            const int* p = (const int*)ei;
            s = p[e]; d = p[N_EDGES + e];
        }
    } else {
        s = d = e - N_EDGES;
    }
}

// ---------------------------------------------------------------------------
// init: zero/-inf scratch + detect edge_index dtype
// ---------------------------------------------------------------------------
__global__ void init_kernel(const int* __restrict__ ei32, float* __restrict__ segmax,
                            float* __restrict__ den, float* __restrict__ acc,
                            float* __restrict__ stats) {
    int i = blockIdx.x * blockDim.x + threadIdx.x;
    if (i == 0) {
        int all0 = 1;
        #pragma unroll 8
        for (int k = 0; k < 64; k++) all0 &= (ei32[2 * k + 1] == 0);
        g_is64 = all0;   // int64: high words of small nonneg values are all zero
    }
    if (i < NH) { segmax[i] = -INFINITY; den[i] = 0.f; }
    if (i < NC) acc[i] = 0.f;
    if (i < 128) stats[i] = 0.f;
}

// ---------------------------------------------------------------------------
// GEMM: XH[N,256] = X[N,64] @ W[64,256]; 64 rows per block, W staged in smem
// ---------------------------------------------------------------------------
__global__ __launch_bounds__(256) void gemm_kernel(const float* __restrict__ X,
                                                   const float* __restrict__ W,
                                                   float* __restrict__ XH) {
    extern __shared__ float sm[];
    float* sW = sm;           // 64*256 = 16384 floats
    float* sX = sm + 16384;   // 64*64  =  4096 floats
    const float4* W4 = (const float4*)W;
    float4* sW4 = (float4*)sW;
    #pragma unroll 4
    for (int i = threadIdx.x; i < 4096; i += 256) sW4[i] = W4[i];

    int row0 = blockIdx.x * 64;
    const float4* X4 = (const float4*)X;
    for (int i = threadIdx.x; i < 1024; i += 256) {
        int r = i >> 4, c4 = i & 15;
        float4 v = make_float4(0.f, 0.f, 0.f, 0.f);
        if (row0 + r < N_NODES) v = X4[(size_t)(row0 + r) * 16 + c4];
        *(float4*)(sX + r * 64 + c4 * 4) = v;
    }
    __syncthreads();

    int cg = threadIdx.x & 63;    // column group: cols cg*4 .. cg*4+3
    int rg = threadIdx.x >> 6;    // row group: rows rg*16 .. rg*16+15
    float acc[16][4];
    #pragma unroll
    for (int r = 0; r < 16; r++) { acc[r][0] = acc[r][1] = acc[r][2] = acc[r][3] = 0.f; }

    const float* xrow = sX + rg * 16 * 64;
    #pragma unroll 8
    for (int k = 0; k < 64; k++) {
        float4 w = *(const float4*)(sW + k * 256 + cg * 4);
        #pragma unroll
        for (int r = 0; r < 16; r++) {
            float a = xrow[r * 64 + k];
            acc[r][0] += a * w.x; acc[r][1] += a * w.y;
            acc[r][2] += a * w.z; acc[r][3] += a * w.w;
        }
    }
    #pragma unroll
    for (int r = 0; r < 16; r++) {
        int row = row0 + rg * 16 + r;
        if (row < N_NODES)
            *(float4*)(XH + (size_t)row * 256 + cg * 4) =
                make_float4(acc[r][0], acc[r][1], acc[r][2], acc[r][3]);
    }
}

// ---------------------------------------------------------------------------
// attention logits: warp per (node, head): al = <xh[n,h,:], a[h,:]>
// ---------------------------------------------------------------------------
__global__ void al_kernel(const float* __restrict__ xh, const float* __restrict__ asrc,
                          const float* __restrict__ adst, float* __restrict__ als,
                          float* __restrict__ ald) {
    int gw = (blockIdx.x * blockDim.x + threadIdx.x) >> 5;
    int lane = threadIdx.x & 31;
    if (gw >= NH) return;
    int n = gw >> 2, h = gw & 3;
    const float2* v2 = (const float2*)(xh + (size_t)n * 256 + h * 64);
    const float2* a2 = (const float2*)(asrc + h * 64);
    const float2* d2 = (const float2*)(adst + h * 64);
    float2 v = v2[lane], a = a2[lane], dd = d2[lane];
    float s1 = v.x * a.x + v.y * a.y;
    float s2 = v.x * dd.x + v.y * dd.y;
    #pragma unroll
    for (int o = 16; o; o >>= 1) {
        s1 += __shfl_xor_sync(0xffffffffu, s1, o);
        s2 += __shfl_xor_sync(0xffffffffu, s2, o);
    }
    if (lane == 0) { als[gw] = s1; ald[gw] = s2; }
}

// ---------------------------------------------------------------------------
// edge pass 1: e = leakyrelu(al_src[s] + al_dst[d]); store e; segment max
// ---------------------------------------------------------------------------
__global__ void edge_max_kernel(const void* __restrict__ ei, const float* __restrict__ als,
                                const float* __restrict__ ald, float* __restrict__ ebuf,
                                float* __restrict__ segmax) {
    int e = blockIdx.x * blockDim.x + threadIdx.x;
    if (e >= E_TOT) return;
    int s, d; edge_endpoints(ei, e, s, d);
    float4 a = *(const float4*)(als + (size_t)s * 4);
    float4 b = *(const float4*)(ald + (size_t)d * 4);
    float4 ev;
    ev.x = lrelu(a.x + b.x); ev.y = lrelu(a.y + b.y);
    ev.z = lrelu(a.z + b.z); ev.w = lrelu(a.w + b.w);
    *(float4*)(ebuf + (size_t)e * 4) = ev;
    float* sm = segmax + (size_t)d * 4;
    atomicMaxF(sm + 0, ev.x); atomicMaxF(sm + 1, ev.y);
    atomicMaxF(sm + 2, ev.z); atomicMaxF(sm + 3, ev.w);
}

// ---------------------------------------------------------------------------
// edge pass 2: p = exp(e - m[d]); denom[d] += p (vector atomic); store p
// ---------------------------------------------------------------------------
__global__ void edge_exp_kernel(const void* __restrict__ ei, float* __restrict__ ebuf,
                                const float* __restrict__ segmax, float* __restrict__ den) {
    int e = blockIdx.x * blockDim.x + threadIdx.x;
    if (e >= E_TOT) return;
    int s, d; edge_endpoints(ei, e, s, d);
    (void)s;
    float4 ev = *(const float4*)(ebuf + (size_t)e * 4);
    float4 m = *(const float4*)(segmax + (size_t)d * 4);
    float4 p;
    p.x = __expf(ev.x - m.x); p.y = __expf(ev.y - m.y);
    p.z = __expf(ev.z - m.z); p.w = __expf(ev.w - m.w);
    *(float4*)(ebuf + (size_t)e * 4) = p;
    atomicAdd((float4*)(den + (size_t)d * 4), p);
}

// ---------------------------------------------------------------------------
// edge pass 3: acc[d,:] += sum_h (0.25 * p_h/denom_h) * xh[s,h,:]
// half-warp (16 lanes) per edge, float4 per lane, vector atomics out
// ---------------------------------------------------------------------------
__global__ void edge_acc_kernel(const void* __restrict__ ei, const float* __restrict__ p,
                                const float* __restrict__ den, const float* __restrict__ xh,
                                float* __restrict__ acc) {
    int t = blockIdx.x * blockDim.x + threadIdx.x;
    int e = t >> 4;
    int lane = t & 15;
    if (e >= E_TOT) return;
    int s, d; edge_endpoints(ei, e, s, d);
    float4 pv = *(const float4*)(p + (size_t)e * 4);
    float4 dv = *(const float4*)(den + (size_t)d * 4);
    float a0 = 0.25f * pv.x / (dv.x + 1e-16f);
    float a1 = 0.25f * pv.y / (dv.y + 1e-16f);
    float a2 = 0.25f * pv.z / (dv.z + 1e-16f);
    float a3 = 0.25f * pv.w / (dv.w + 1e-16f);
    const float4* x4 = (const float4*)xh + (size_t)s * 64;
    float4 r = make_float4(0.f, 0.f, 0.f, 0.f);
    float4 v;
    v = x4[lane];       r.x += a0 * v.x; r.y += a0 * v.y; r.z += a0 * v.z; r.w += a0 * v.w;
    v = x4[16 + lane];  r.x += a1 * v.x; r.y += a1 * v.y; r.z += a1 * v.z; r.w += a1 * v.w;
    v = x4[32 + lane];  r.x += a2 * v.x; r.y += a2 * v.y; r.z += a2 * v.z; r.w += a2 * v.w;
    v = x4[48 + lane];  r.x += a3 * v.x; r.y += a3 * v.y; r.z += a3 * v.z; r.w += a3 * v.w;
    atomicAdd((float4*)acc + (size_t)d * 16 + lane, r);
}

// ---------------------------------------------------------------------------
// bias: saved = acc + b
// ---------------------------------------------------------------------------
__global__ void add_bias_kernel(const float* __restrict__ acc, const float* __restrict__ b,
                                float* __restrict__ saved) {
    int i = blockIdx.x * blockDim.x + threadIdx.x;
    if (i >= NC) return;
    saved[i] = acc[i] + b[i & 63];
}

// ---------------------------------------------------------------------------
// BN stats: per-channel sum & sumsq via block partials + atomics
// ---------------------------------------------------------------------------
__global__ void bn_stats_kernel(const float* __restrict__ xs, float* __restrict__ stats) {
    int c = threadIdx.x & 63, ry = threadIdx.x >> 6;   // blockDim = 256
    float s = 0.f, s2 = 0.f;
    for (int r = blockIdx.x * 4 + ry; r < N_NODES; r += gridDim.x * 4) {
        float v = xs[(size_t)r * 64 + c];
        s += v; s2 += v * v;
    }
    __shared__ float sh[256], sh2[256];
    sh[threadIdx.x] = s; sh2[threadIdx.x] = s2;
    __syncthreads();
    if (ry == 0) {
        s  = sh[c]  + sh[64 + c]  + sh[128 + c]  + sh[192 + c];
        s2 = sh2[c] + sh2[64 + c] + sh2[128 + c] + sh2[192 + c];
        atomicAdd(&stats[c], s);
        atomicAdd(&stats[64 + c], s2);
    }
}

// ---------------------------------------------------------------------------
// BN normalize + relu
// ---------------------------------------------------------------------------
__global__ void bn_norm_kernel(const float* __restrict__ xs, const float* __restrict__ stats,
                               const float* __restrict__ gamma, const float* __restrict__ beta,
                               float* __restrict__ out) {
    int i = blockIdx.x * blockDim.x + threadIdx.x;
    if (i >= NC) return;
    int c = i & 63;
    const float invN = 1.f / (float)N_NODES;
    float mu = stats[c] * invN;
    float var = stats[64 + c] * invN - mu * mu;
    float rs = rsqrtf(var + 1e-5f);
    float y = gamma[c] * (xs[i] - mu) * rs + beta[c];
    out[i] = fmaxf(y, 0.f);
}

// ---------------------------------------------------------------------------
// host
// ---------------------------------------------------------------------------
static void run_layer(const float* xin, const void* ei, const int* ei32,
                      const float* W, const float* as, const float* ad, const float* b,
                      const float* gm, const float* bt,
                      float* saved_out, float* final_out, float* S) {
    float* xh     = S + OFF_XH;
    float* als    = S + OFF_ALS;
    float* ald    = S + OFF_ALD;
    float* segmax = S + OFF_MAX;
    float* den    = S + OFF_DEN;
    float* ebuf   = S + OFF_E;
    float* acc    = S + OFF_ACC;
    float* stats  = S + OFF_STATS;

    init_kernel<<<(NC + 255) / 256, 256>>>(ei32, segmax, den, acc, stats);
    gemm_kernel<<<(N_NODES + 63) / 64, 256, 81920>>>(xin, W, xh);
    al_kernel<<<(NH * 32 + 255) / 256, 256>>>(xh, as, ad, als, ald);
    edge_max_kernel<<<(E_TOT + 255) / 256, 256>>>(ei, als, ald, ebuf, segmax);
    edge_exp_kernel<<<(E_TOT + 255) / 256, 256>>>(ei, ebuf, segmax, den);
    edge_acc_kernel<<<(E_TOT * 16 + 255) / 256, 256>>>(ei, ebuf, den, xh, acc);
    add_bias_kernel<<<(NC + 255) / 256, 256>>>(acc, b, saved_out);
    bn_stats_kernel<<<256, 256>>>(saved_out, stats);
    bn_norm_kernel<<<(NC + 255) / 256, 256>>>(saved_out, stats, gm, bt, final_out);
}

extern "C" void kernel_launch(void* const* d_in, const int* in_sizes, int n_in,
                              void* d_out, int out_size) {
    const float* x   = (const float*)d_in[0];
    const void*  ei  = d_in[1];                 // int32 or int64; detected on device
    const int*   ei32 = (const int*)d_in[1];
    const float* W0  = (const float*)d_in[3];
    const float* as0 = (const float*)d_in[4];
    const float* ad0 = (const float*)d_in[5];
    const float* b0  = (const float*)d_in[6];
    const float* g0  = (const float*)d_in[7];
    const float* bt0 = (const float*)d_in[8];
    const float* W1  = (const float*)d_in[9];
    const float* as1 = (const float*)d_in[10];
    const float* ad1 = (const float*)d_in[11];
    const float* b1  = (const float*)d_in[12];
    const float* g1  = (const float*)d_in[13];
    const float* bt1 = (const float*)d_in[14];

    void* sp = nullptr;
    cudaGetSymbolAddress(&sp, g_scratch);
    float* S = (float*)sp;

    cudaFuncSetAttribute(gemm_kernel, cudaFuncAttributeMaxDynamicSharedMemorySize, 81920);

    float* out_final = (float*)d_out;
    float* out_saved = out_final + NC;

    // layer 1: saved in-place over acc (acc + b), BN output -> h1
    run_layer(x, ei, ei32, W0, as0, ad0, b0, g0, bt0,
              S + OFF_ACC, S + OFF_H1, S);
    // layer 2: input h1; saved -> second half of d_out; final -> first half
    run_layer(S + OFF_H1, ei, ei32, W1, as1, ad1, b1, g1, bt1,
              out_saved, out_final, S);
}

// round 4
// speedup vs baseline: 1.0516x; 1.0516x over previous
#include <cuda_runtime.h>
#include <math.h>

#define N_NODES 50000
#define N_EDGES 800000
#define E_TOT   850000          // + self loops
#define C       64
#define NC      (N_NODES * C)   // 3,200,000
#define NH      (N_NODES * 4)   // 200,000

// ---- scratch layout (floats; ints aliased) ----
#define OFF_XH    0
#define SZ_XH     (N_NODES * 4 * C)        // 12,800,000
#define OFF_ALS   (OFF_XH + SZ_XH)
#define OFF_ALD   (OFF_ALS + NH)
#define OFF_H1    (OFF_ALD + NH)
#define OFF_STATS (OFF_H1 + NC)            // 128 finalized stats
#define OFF_PART  (OFF_STATS + 128)        // 256 blocks * 128 partials
#define OFF_DEG   (OFF_PART + 256*128)     // ints
#define OFF_ROWP  (OFF_DEG + N_NODES)
#define OFF_CUR   (OFF_ROWP + N_NODES)
#define OFF_CSRC  (OFF_CUR + N_NODES)
#define SCRATCH_TOTAL (OFF_CSRC + E_TOT)

__device__ __align__(16) float g_scratch[SCRATCH_TOTAL];
__device__ int g_is64;

__device__ __forceinline__ float lrelu(float x) { return x > 0.f ? x : 0.2f * x; }

__device__ __forceinline__ void edge_endpoints(const void* ei, int e, int& s, int& d) {
    if (e < N_EDGES) {
        if (g_is64) {
            const long long* p = (const long long*)ei;
            s = (int)p[e]; d = (int)p[N_EDGES + e];
        } else {
            const int* p = (const int*)ei;
            s = p[e]; d = p[N_EDGES + e];
        }
    } else {
        s = d = e - N_EDGES;
    }
}

// ---------------------------------------------------------------------------
// init: zero degree counters + detect edge dtype
// ---------------------------------------------------------------------------
__global__ void init_kernel(const int* __restrict__ ei32, int* __restrict__ deg) {
    int i = blockIdx.x * blockDim.x + threadIdx.x;
    if (i == 0) {
        int all0 = 1;
        #pragma unroll 8
        for (int k = 0; k < 64; k++) all0 &= (ei32[2 * k + 1] == 0);
        g_is64 = all0;
    }
    if (i < N_NODES) deg[i] = 0;
}

// ---------------------------------------------------------------------------
// CSR build: histogram by dst
// ---------------------------------------------------------------------------
__global__ void hist_kernel(const void* __restrict__ ei, int* __restrict__ deg) {
    int e = blockIdx.x * blockDim.x + threadIdx.x;
    if (e >= E_TOT) return;
    int s, d; edge_endpoints(ei, e, s, d); (void)s;
    atomicAdd(&deg[d], 1);
}

// single-block exclusive scan over 50000 degrees
#define SCAN_T 1024
#define SCAN_CHUNK 49     // 1024*49 = 50176 >= 50000
__global__ __launch_bounds__(SCAN_T) void scan_kernel(const int* __restrict__ deg,
                                                      int* __restrict__ row_ptr,
                                                      int* __restrict__ cursor) {
    __shared__ int sm[SCAN_T];
    int t = threadIdx.x;
    int base = t * SCAN_CHUNK;
    int s = 0;
    for (int i = 0; i < SCAN_CHUNK; i++) {
        int idx = base + i;
        if (idx < N_NODES) s += deg[idx];
    }
    sm[t] = s;
    __syncthreads();
    for (int off = 1; off < SCAN_T; off <<= 1) {
        int v = 0;
        if (t >= off) v = sm[t - off];
        __syncthreads();
        if (t >= off) sm[t] += v;
        __syncthreads();
    }
    int ex = (t == 0) ? 0 : sm[t - 1];
    for (int i = 0; i < SCAN_CHUNK; i++) {
        int idx = base + i;
        if (idx < N_NODES) {
            row_ptr[idx] = ex;
            cursor[idx] = ex;
            ex += deg[idx];
        }
    }
}

__global__ void scatter_kernel(const void* __restrict__ ei, int* __restrict__ cursor,
                               int* __restrict__ csr_src) {
    int e = blockIdx.x * blockDim.x + threadIdx.x;
    if (e >= E_TOT) return;
    int s, d; edge_endpoints(ei, e, s, d);
    int pos = atomicAdd(&cursor[d], 1);
    csr_src[pos] = s;
}

// ---------------------------------------------------------------------------
// GEMM: XH[N,256] = X[N,64] @ W[64,256]; 64 rows per block, W staged in smem
// ---------------------------------------------------------------------------
__global__ __launch_bounds__(256) void gemm_kernel(const float* __restrict__ X,
                                                   const float* __restrict__ W,
                                                   float* __restrict__ XH) {
    extern __shared__ float sm[];
    float* sW = sm;           // 64*256 = 16384 floats
    float* sX = sm + 16384;   // 64*64  =  4096 floats
    const float4* W4 = (const float4*)W;
    float4* sW4 = (float4*)sW;
    #pragma unroll 4
    for (int i = threadIdx.x; i < 4096; i += 256) sW4[i] = W4[i];

    int row0 = blockIdx.x * 64;
    const float4* X4 = (const float4*)X;
    for (int i = threadIdx.x; i < 1024; i += 256) {
        int r = i >> 4, c4 = i & 15;
        float4 v = make_float4(0.f, 0.f, 0.f, 0.f);
        if (row0 + r < N_NODES) v = X4[(size_t)(row0 + r) * 16 + c4];
        *(float4*)(sX + r * 64 + c4 * 4) = v;
    }
    __syncthreads();

    int cg = threadIdx.x & 63;
    int rg = threadIdx.x >> 6;
    float acc[16][4];
    #pragma unroll
    for (int r = 0; r < 16; r++) { acc[r][0] = acc[r][1] = acc[r][2] = acc[r][3] = 0.f; }

    const float* xrow = sX + rg * 16 * 64;
    #pragma unroll 8
    for (int k = 0; k < 64; k++) {
        float4 w = *(const float4*)(sW + k * 256 + cg * 4);
        #pragma unroll
        for (int r = 0; r < 16; r++) {
            float a = xrow[r * 64 + k];
            acc[r][0] += a * w.x; acc[r][1] += a * w.y;
            acc[r][2] += a * w.z; acc[r][3] += a * w.w;
        }
    }
    #pragma unroll
    for (int r = 0; r < 16; r++) {
        int row = row0 + rg * 16 + r;
        if (row < N_NODES)
            *(float4*)(XH + (size_t)row * 256 + cg * 4) =
                make_float4(acc[r][0], acc[r][1], acc[r][2], acc[r][3]);
    }
}

// ---------------------------------------------------------------------------
// attention logits: warp per (node, head)
// ---------------------------------------------------------------------------
__global__ void al_kernel(const float* __restrict__ xh, const float* __restrict__ asrc,
                          const float* __restrict__ adst, float* __restrict__ als,
                          float* __restrict__ ald) {
    int gw = (blockIdx.x * blockDim.x + threadIdx.x) >> 5;
    int lane = threadIdx.x & 31;
    if (gw >= NH) return;
    int n = gw >> 2, h = gw & 3;
    const float2* v2 = (const float2*)(xh + (size_t)n * 256 + h * 64);
    const float2* a2 = (const float2*)(asrc + h * 64);
    const float2* d2 = (const float2*)(adst + h * 64);
    float2 v = v2[lane], a = a2[lane], dd = d2[lane];
    float s1 = v.x * a.x + v.y * a.y;
    float s2 = v.x * dd.x + v.y * dd.y;
    #pragma unroll
    for (int o = 16; o; o >>= 1) {
        s1 += __shfl_xor_sync(0xffffffffu, s1, o);
        s2 += __shfl_xor_sync(0xffffffffu, s2, o);
    }
    if (lane == 0) { als[gw] = s1; ald[gw] = s2; }
}

// ---------------------------------------------------------------------------
// fused per-dst softmax + gather-accumulate + bias. Warp per destination node.
// No max subtraction (logits are O(1); exp cannot overflow), no atomics.
// ---------------------------------------------------------------------------
__global__ __launch_bounds__(256) void dst_kernel(const int* __restrict__ row_ptr,
                                                  const int* __restrict__ deg,
                                                  const int* __restrict__ csr_src,
                                                  const float* __restrict__ als,
                                                  const float* __restrict__ ald,
                                                  const float* __restrict__ xh,
                                                  const float* __restrict__ bias,
                                                  float* __restrict__ saved) {
    int w = (blockIdx.x * blockDim.x + threadIdx.x) >> 5;
    int lane = threadIdx.x & 31;
    if (w >= N_NODES) return;
    int d = w;
    int start = row_ptr[d];
    int n = deg[d];
    float4 ad = *(const float4*)(ald + (size_t)d * 4);

    // pass 1: denominator per head
    float4 den = make_float4(0.f, 0.f, 0.f, 0.f);
    for (int base = 0; base < n; base += 32) {
        int j = base + lane;
        float4 p = make_float4(0.f, 0.f, 0.f, 0.f);
        if (j < n) {
            int s = csr_src[start + j];
            float4 a = *(const float4*)(als + (size_t)s * 4);
            p.x = __expf(lrelu(a.x + ad.x));
            p.y = __expf(lrelu(a.y + ad.y));
            p.z = __expf(lrelu(a.z + ad.z));
            p.w = __expf(lrelu(a.w + ad.w));
        }
        #pragma unroll
        for (int o = 16; o; o >>= 1) {
            p.x += __shfl_xor_sync(0xffffffffu, p.x, o);
            p.y += __shfl_xor_sync(0xffffffffu, p.y, o);
            p.z += __shfl_xor_sync(0xffffffffu, p.z, o);
            p.w += __shfl_xor_sync(0xffffffffu, p.w, o);
        }
        den.x += p.x; den.y += p.y; den.z += p.z; den.w += p.w;
    }
    float4 inv;
    inv.x = 0.25f / (den.x + 1e-16f);
    inv.y = 0.25f / (den.y + 1e-16f);
    inv.z = 0.25f / (den.z + 1e-16f);
    inv.w = 0.25f / (den.w + 1e-16f);

    // pass 2: accumulate. lane owns channels (2*lane, 2*lane+1) for all heads.
    float2 r0 = make_float2(0.f, 0.f), r1 = r0, r2 = r0, r3 = r0;
    for (int base = 0; base < n; base += 32) {
        int j = base + lane;
        int s = 0;
        float4 p = make_float4(0.f, 0.f, 0.f, 0.f);
        if (j < n) {
            s = csr_src[start + j];
            float4 a = *(const float4*)(als + (size_t)s * 4);
            p.x = __expf(lrelu(a.x + ad.x)) * inv.x;
            p.y = __expf(lrelu(a.y + ad.y)) * inv.y;
            p.z = __expf(lrelu(a.z + ad.z)) * inv.z;
            p.w = __expf(lrelu(a.w + ad.w)) * inv.w;
        }
        int cnt = n - base; if (cnt > 32) cnt = 32;
        for (int jj = 0; jj < cnt; jj++) {
            int ss   = __shfl_sync(0xffffffffu, s, jj);
            float a0 = __shfl_sync(0xffffffffu, p.x, jj);
            float a1 = __shfl_sync(0xffffffffu, p.y, jj);
            float a2 = __shfl_sync(0xffffffffu, p.z, jj);
            float a3 = __shfl_sync(0xffffffffu, p.w, jj);
            const float2* xp = (const float2*)xh + (size_t)ss * 128 + lane;
            float2 v0 = xp[0], v1 = xp[32], v2 = xp[64], v3 = xp[96];
            r0.x += a0 * v0.x; r0.y += a0 * v0.y;
            r1.x += a1 * v1.x; r1.y += a1 * v1.y;
            r2.x += a2 * v2.x; r2.y += a2 * v2.y;
            r3.x += a3 * v3.x; r3.y += a3 * v3.y;
        }
    }
    float2 o;
    o.x = r0.x + r1.x + r2.x + r3.x;
    o.y = r0.y + r1.y + r2.y + r3.y;
    float2 bb = *((const float2*)bias + lane);
    o.x += bb.x; o.y += bb.y;
    *((float2*)(saved + (size_t)d * 64) + lane) = o;
}

// ---------------------------------------------------------------------------
// BN stats: per-block partials (no atomics)
// ---------------------------------------------------------------------------
__global__ void bn_stats_kernel(const float* __restrict__ xs, float* __restrict__ part) {
    int c = threadIdx.x & 63, ry = threadIdx.x >> 6;   // blockDim = 256
    float s = 0.f, s2 = 0.f;
    for (int r = blockIdx.x * 4 + ry; r < N_NODES; r += gridDim.x * 4) {
        float v = xs[(size_t)r * 64 + c];
        s += v; s2 += v * v;
    }
    __shared__ float sh[256], sh2[256];
    sh[threadIdx.x] = s; sh2[threadIdx.x] = s2;
    __syncthreads();
    if (ry == 0) {
        s  = sh[c]  + sh[64 + c]  + sh[128 + c]  + sh[192 + c];
        s2 = sh2[c] + sh2[64 + c] + sh2[128 + c] + sh2[192 + c];
        part[blockIdx.x * 128 + c]      = s;
        part[blockIdx.x * 128 + 64 + c] = s2;
    }
}

__global__ void bn_finalize_kernel(const float* __restrict__ part, float* __restrict__ stats) {
    int c = threadIdx.x;   // 128 threads
    float s = 0.f;
    for (int b = 0; b < 256; b++) s += part[b * 128 + c];
    stats[c] = s;
}

// ---------------------------------------------------------------------------
// BN normalize + relu
// ---------------------------------------------------------------------------
__global__ void bn_norm_kernel(const float* __restrict__ xs, const float* __restrict__ stats,
                               const float* __restrict__ gamma, const float* __restrict__ beta,
                               float* __restrict__ out) {
    int i = blockIdx.x * blockDim.x + threadIdx.x;
    if (i >= NC) return;
    int c = i & 63;
    const float invN = 1.f / (float)N_NODES;
    float mu = stats[c] * invN;
    float var = stats[64 + c] * invN - mu * mu;
    float rs = rsqrtf(var + 1e-5f);
    float y = gamma[c] * (xs[i] - mu) * rs + beta[c];
    out[i] = fmaxf(y, 0.f);
}

// ---------------------------------------------------------------------------
// host
// ---------------------------------------------------------------------------
static void run_layer(const float* xin, const float* W, const float* as, const float* ad,
                      const float* b, const float* gm, const float* bt,
                      float* saved_out, float* final_out, float* S) {
    float* xh    = S + OFF_XH;
    float* als   = S + OFF_ALS;
    float* ald   = S + OFF_ALD;
    float* stats = S + OFF_STATS;
    float* part  = S + OFF_PART;
    int* deg     = (int*)(S + OFF_DEG);
    int* rowp    = (int*)(S + OFF_ROWP);
    int* csrc    = (int*)(S + OFF_CSRC);

    gemm_kernel<<<(N_NODES + 63) / 64, 256, 81920>>>(xin, W, xh);
    al_kernel<<<(NH * 32 + 255) / 256, 256>>>(xh, as, ad, als, ald);
    dst_kernel<<<(N_NODES * 32 + 255) / 256, 256>>>(rowp, deg, csrc, als, ald, xh, b, saved_out);
    bn_stats_kernel<<<256, 256>>>(saved_out, part);
    bn_finalize_kernel<<<1, 128>>>(part, stats);
    bn_norm_kernel<<<(NC + 255) / 256, 256>>>(saved_out, stats, gm, bt, final_out);
}

extern "C" void kernel_launch(void* const* d_in, const int* in_sizes, int n_in,
                              void* d_out, int out_size) {
    const float* x   = (const float*)d_in[0];
    const void*  ei  = d_in[1];
    const int*   ei32 = (const int*)d_in[1];
    const float* W0  = (const float*)d_in[3];
    const float* as0 = (const float*)d_in[4];
    const float* ad0 = (const float*)d_in[5];
    const float* b0  = (const float*)d_in[6];
    const float* g0  = (const float*)d_in[7];
    const float* bt0 = (const float*)d_in[8];
    const float* W1  = (const float*)d_in[9];
    const float* as1 = (const float*)d_in[10];
    const float* ad1 = (const float*)d_in[11];
    const float* b1  = (const float*)d_in[12];
    const float* g1  = (const float*)d_in[13];
    const float* bt1 = (const float*)d_in[14];

    void* sp = nullptr;
    cudaGetSymbolAddress(&sp, g_scratch);
    float* S = (float*)sp;
    int* deg  = (int*)(S + OFF_DEG);
    int* rowp = (int*)(S + OFF_ROWP);
    int* cur  = (int*)(S + OFF_CUR);
    int* csrc = (int*)(S + OFF_CSRC);

    cudaFuncSetAttribute(gemm_kernel, cudaFuncAttributeMaxDynamicSharedMemorySize, 81920);

    // CSR build (edges identical for both layers — build once)
    init_kernel<<<(N_NODES + 255) / 256, 256>>>(ei32, deg);
    hist_kernel<<<(E_TOT + 255) / 256, 256>>>(ei, deg);
    scan_kernel<<<1, SCAN_T>>>(deg, rowp, cur);
    scatter_kernel<<<(E_TOT + 255) / 256, 256>>>(ei, cur, csrc);

    float* out_final = (float*)d_out;
    float* out_saved = out_final + NC;

    // layer 1: saved -> scratch (reuse H1 region after BN reads it? need both) —
    // saved1 only feeds BN; keep it in PART-safe area: use out_saved temporarily? No:
    // use d_out's saved half as temp for layer1, overwritten by layer2. Safe: layer1
    // writes saved->out_saved, BN reads it, then layer2 overwrites out_saved.
    run_layer(x, W0, as0, ad0, b0, g0, bt0, out_saved, S + OFF_H1, S);
    run_layer(S + OFF_H1, W1, as1, ad1, b1, g1, bt1, out_saved, out_final, S);
}

// round 9
// speedup vs baseline: 1.0655x; 1.0132x over previous
#include <cuda_runtime.h>
#include <math.h>

#define N_NODES 50000
#define N_EDGES 800000
#define E_TOT   850000          // + self loops
#define C       64
#define NC      (N_NODES * C)   // 3,200,000
#define NH      (N_NODES * 4)   // 200,000

// ---- scratch layout (floats; ints aliased) ----
#define OFF_AGG   0
#define SZ_AGG    (N_NODES * 256)          // 12,800,000
#define OFF_ALS   (OFF_AGG + SZ_AGG)
#define OFF_ALD   (OFF_ALS + NH)
#define OFF_H1    (OFF_ALD + NH)
#define OFF_STATS (OFF_H1 + NC)            // 128
#define OFF_PART  (OFF_STATS + 128)        // 256*128
#define OFF_WA    (OFF_PART + 256*128)     // 512 (wa_src[4][64], wa_dst[4][64])
#define OFF_DEG   (OFF_WA + 512)           // ints
#define OFF_ROWP  (OFF_DEG + N_NODES)
#define OFF_CUR   (OFF_ROWP + N_NODES)
#define OFF_CSRC  (OFF_CUR + N_NODES)
#define SCRATCH_TOTAL (OFF_CSRC + E_TOT)

__device__ __align__(16) float g_scratch[SCRATCH_TOTAL];
__device__ int g_is64;

__device__ __forceinline__ float lrelu(float x) { return x > 0.f ? x : 0.2f * x; }

__device__ __forceinline__ void edge_endpoints(const void* ei, int e, int& s, int& d) {
    if (e < N_EDGES) {
        if (g_is64) {
            const long long* p = (const long long*)ei;
            s = (int)p[e]; d = (int)p[N_EDGES + e];
        } else {
            const int* p = (const int*)ei;
            s = p[e]; d = p[N_EDGES + e];
        }
    } else {
        s = d = e - N_EDGES;
    }
}

// ---------------------------------------------------------------------------
// init + CSR build (once; edges shared by both layers)
// ---------------------------------------------------------------------------
__global__ void init_kernel(const int* __restrict__ ei32, int* __restrict__ deg) {
    int i = blockIdx.x * blockDim.x + threadIdx.x;
    if (i == 0) {
        int all0 = 1;
        #pragma unroll 8
        for (int k = 0; k < 64; k++) all0 &= (ei32[2 * k + 1] == 0);
        g_is64 = all0;
    }
    if (i < N_NODES) deg[i] = 0;
}

__global__ void hist_kernel(const void* __restrict__ ei, int* __restrict__ deg) {
    int e = blockIdx.x * blockDim.x + threadIdx.x;
    if (e >= E_TOT) return;
    int s, d; edge_endpoints(ei, e, s, d); (void)s;
    atomicAdd(&deg[d], 1);
}

#define SCAN_T 1024
#define SCAN_CHUNK 49
__global__ __launch_bounds__(SCAN_T) void scan_kernel(const int* __restrict__ deg,
                                                      int* __restrict__ row_ptr,
                                                      int* __restrict__ cursor) {
    __shared__ int sm[SCAN_T];
    int t = threadIdx.x;
    int base = t * SCAN_CHUNK;
    int s = 0;
    for (int i = 0; i < SCAN_CHUNK; i++) {
        int idx = base + i;
        if (idx < N_NODES) s += deg[idx];
    }
    sm[t] = s;
    __syncthreads();
    for (int off = 1; off < SCAN_T; off <<= 1) {
        int v = 0;
        if (t >= off) v = sm[t - off];
        __syncthreads();
        if (t >= off) sm[t] += v;
        __syncthreads();
    }
    int ex = (t == 0) ? 0 : sm[t - 1];
    for (int i = 0; i < SCAN_CHUNK; i++) {
        int idx = base + i;
        if (idx < N_NODES) {
            row_ptr[idx] = ex;
            cursor[idx] = ex;
            ex += deg[idx];
        }
    }
}

__global__ void scatter_kernel(const void* __restrict__ ei, int* __restrict__ cursor,
                               int* __restrict__ csr_src) {
    int e = blockIdx.x * blockDim.x + threadIdx.x;
    if (e >= E_TOT) return;
    int s, d; edge_endpoints(ei, e, s, d);
    int pos = atomicAdd(&cursor[d], 1);
    csr_src[pos] = s;
}

// ---------------------------------------------------------------------------
// wa precompute: wa_src[h][ci] = sum_c W[ci, h*64+c] * a_src[h,c]  (and dst)
// ---------------------------------------------------------------------------
__global__ void wa_kernel(const float* __restrict__ W, const float* __restrict__ asrc,
                          const float* __restrict__ adst, float* __restrict__ wa) {
    int t = threadIdx.x;            // 256 threads
    int h = t >> 6, ci = t & 63;
    float s = 0.f, d = 0.f;
    #pragma unroll 8
    for (int c = 0; c < 64; c++) {
        float w = W[ci * 256 + h * 64 + c];
        s += w * asrc[h * 64 + c];
        d += w * adst[h * 64 + c];
    }
    wa[h * 64 + ci] = s;
    wa[256 + h * 64 + ci] = d;
}

// ---------------------------------------------------------------------------
// attention logits directly from x: als[n,h] = x[n]·wa_src[h]
// ---------------------------------------------------------------------------
__global__ __launch_bounds__(256) void al_kernel(const float* __restrict__ x,
                                                 const float* __restrict__ wa,
                                                 float* __restrict__ als,
                                                 float* __restrict__ ald) {
    __shared__ float swa[512];
    for (int i = threadIdx.x; i < 512; i += 256) swa[i] = wa[i];
    __syncthreads();
    int n = blockIdx.x * blockDim.x + threadIdx.x;
    if (n >= N_NODES) return;
    float xv[64];
    const float4* xr = (const float4*)(x + (size_t)n * 64);
    #pragma unroll
    for (int i = 0; i < 16; i++) {
        float4 v = xr[i];
        xv[4 * i] = v.x; xv[4 * i + 1] = v.y; xv[4 * i + 2] = v.z; xv[4 * i + 3] = v.w;
    }
    float rs[4], rd[4];
    #pragma unroll
    for (int h = 0; h < 4; h++) {
        float s = 0.f, d = 0.f;
        #pragma unroll 8
        for (int c = 0; c < 64; c++) {
            s += xv[c] * swa[h * 64 + c];
            d += xv[c] * swa[256 + h * 64 + c];
        }
        rs[h] = s; rd[h] = d;
    }
    *(float4*)(als + (size_t)n * 4) = make_float4(rs[0], rs[1], rs[2], rs[3]);
    *(float4*)(ald + (size_t)n * 4) = make_float4(rd[0], rd[1], rd[2], rd[3]);
}

// ---------------------------------------------------------------------------
// fused per-dst softmax + x-gather-accumulate. Warp per destination node.
// agg[d, h*64+c] = sum_e alpha_eh * x[s_e, c]   (alpha WITHOUT the 1/4 mean;
// the head-mean factor is applied exactly once in gemm2's epilogue)
// ---------------------------------------------------------------------------
__global__ __launch_bounds__(256) void dst_kernel(const int* __restrict__ row_ptr,
                                                  const int* __restrict__ deg,
                                                  const int* __restrict__ csr_src,
                                                  const float* __restrict__ als,
                                                  const float* __restrict__ ald,
                                                  const float* __restrict__ x,
                                                  float* __restrict__ agg) {
    int w = (blockIdx.x * blockDim.x + threadIdx.x) >> 5;
    int lane = threadIdx.x & 31;
    if (w >= N_NODES) return;
    int start = row_ptr[w];
    int n = deg[w];
    float4 ad = *(const float4*)(ald + (size_t)w * 4);

    // pass 1: denominator per head
    float4 den = make_float4(0.f, 0.f, 0.f, 0.f);
    for (int base = 0; base < n; base += 32) {
        int j = base + lane;
        float4 p = make_float4(0.f, 0.f, 0.f, 0.f);
        if (j < n) {
            int s = csr_src[start + j];
            float4 a = *(const float4*)(als + (size_t)s * 4);
            p.x = __expf(lrelu(a.x + ad.x));
            p.y = __expf(lrelu(a.y + ad.y));
            p.z = __expf(lrelu(a.z + ad.z));
            p.w = __expf(lrelu(a.w + ad.w));
        }
        #pragma unroll
        for (int o = 16; o; o >>= 1) {
            p.x += __shfl_xor_sync(0xffffffffu, p.x, o);
            p.y += __shfl_xor_sync(0xffffffffu, p.y, o);
            p.z += __shfl_xor_sync(0xffffffffu, p.z, o);
            p.w += __shfl_xor_sync(0xffffffffu, p.w, o);
        }
        den.x += p.x; den.y += p.y; den.z += p.z; den.w += p.w;
    }
    float4 inv;
    inv.x = 1.0f / (den.x + 1e-16f);
    inv.y = 1.0f / (den.y + 1e-16f);
    inv.z = 1.0f / (den.z + 1e-16f);
    inv.w = 1.0f / (den.w + 1e-16f);

    // pass 2: accumulate x rows. Lane owns channels (2*lane, 2*lane+1), 4 heads.
    float2 r0 = make_float2(0.f, 0.f), r1 = r0, r2 = r0, r3 = r0;
    for (int base = 0; base < n; base += 32) {
        int j = base + lane;
        int s = 0;
        float4 p = make_float4(0.f, 0.f, 0.f, 0.f);
        if (j < n) {
            s = csr_src[start + j];
            float4 a = *(const float4*)(als + (size_t)s * 4);
            p.x = __expf(lrelu(a.x + ad.x)) * inv.x;
            p.y = __expf(lrelu(a.y + ad.y)) * inv.y;
            p.z = __expf(lrelu(a.z + ad.z)) * inv.z;
            p.w = __expf(lrelu(a.w + ad.w)) * inv.w;
        }
        int cnt = n - base; if (cnt > 32) cnt = 32;
        for (int jj = 0; jj < cnt; jj++) {
            int ss   = __shfl_sync(0xffffffffu, s, jj);
            float a0 = __shfl_sync(0xffffffffu, p.x, jj);
            float a1 = __shfl_sync(0xffffffffu, p.y, jj);
            float a2 = __shfl_sync(0xffffffffu, p.z, jj);
            float a3 = __shfl_sync(0xffffffffu, p.w, jj);
            float2 v = *((const float2*)(x + (size_t)ss * 64) + lane);
            r0.x += a0 * v.x; r0.y += a0 * v.y;
            r1.x += a1 * v.x; r1.y += a1 * v.y;
            r2.x += a2 * v.x; r2.y += a2 * v.y;
            r3.x += a3 * v.x; r3.y += a3 * v.y;
        }
    }
    float2* ag = (float2*)(agg + (size_t)w * 256);
    ag[lane] = r0; ag[32 + lane] = r1; ag[64 + lane] = r2; ag[96 + lane] = r3;
}

// ---------------------------------------------------------------------------
// GEMM2: saved[N,64] = 0.25 * agg[N,256] @ Wcat[256,64] + bias
// Wcat[h*64+c, j] = W[c, h*64+j] (indexed on the fly from W staged in smem)
// 128 rows per block; A staged transposed (sA_t[k][row], stride 132).
// ---------------------------------------------------------------------------
#define G2_ROWS 128
__global__ __launch_bounds__(256) void gemm2_kernel(const float* __restrict__ agg,
                                                    const float* __restrict__ W,
                                                    const float* __restrict__ bias,
                                                    float* __restrict__ out) {
    extern __shared__ float sm[];
    float* sW = sm;              // 16384 floats
    float* sA = sm + 16384;      // 64 * 132 floats per k-chunk
    const float4* W4 = (const float4*)W;
    float4* sW4 = (float4*)sW;
    #pragma unroll 4
    for (int i = threadIdx.x; i < 4096; i += 256) sW4[i] = W4[i];

    int row0 = blockIdx.x * G2_ROWS;
    int cg = threadIdx.x & 15;    // 4 cols each -> 64 cols
    int rg = threadIdx.x >> 4;    // 8 rows each -> 128 rows
    float acc[8][4];
    #pragma unroll
    for (int r = 0; r < 8; r++) { acc[r][0] = acc[r][1] = acc[r][2] = acc[r][3] = 0.f; }

    for (int kc = 0; kc < 4; kc++) {
        __syncthreads();
        // stage agg[row0..row0+128)[kc*64..+64) transposed into sA
        for (int i = threadIdx.x; i < 2048; i += 256) {
            int r = i >> 4, c4 = i & 15;
            float4 v = make_float4(0.f, 0.f, 0.f, 0.f);
            int row = row0 + r;
            if (row < N_NODES) v = *(const float4*)(agg + (size_t)row * 256 + kc * 64 + c4 * 4);
            sA[(c4 * 4 + 0) * 132 + r] = v.x;
            sA[(c4 * 4 + 1) * 132 + r] = v.y;
            sA[(c4 * 4 + 2) * 132 + r] = v.z;
            sA[(c4 * 4 + 3) * 132 + r] = v.w;
        }
        __syncthreads();
        const float* wbase = sW + kc * 64;
        #pragma unroll 4
        for (int k = 0; k < 64; k++) {
            float4 b4 = *(const float4*)(wbase + k * 256 + cg * 4);
            const float* arow = sA + k * 132 + rg * 8;
            float4 a0 = *(const float4*)(arow);
            float4 a1 = *(const float4*)(arow + 4);
            float av[8] = {a0.x, a0.y, a0.z, a0.w, a1.x, a1.y, a1.z, a1.w};
            #pragma unroll
            for (int r = 0; r < 8; r++) {
                acc[r][0] += av[r] * b4.x;
                acc[r][1] += av[r] * b4.y;
                acc[r][2] += av[r] * b4.z;
                acc[r][3] += av[r] * b4.w;
            }
        }
    }
    float4 bb = *((const float4*)bias + cg);
    #pragma unroll
    for (int r = 0; r < 8; r++) {
        int row = row0 + rg * 8 + r;
        if (row < N_NODES) {
            float4 o;
            o.x = 0.25f * acc[r][0] + bb.x;
            o.y = 0.25f * acc[r][1] + bb.y;
            o.z = 0.25f * acc[r][2] + bb.z;
            o.w = 0.25f * acc[r][3] + bb.w;
            *(float4*)(out + (size_t)row * 64 + cg * 4) = o;
        }
    }
}

// ---------------------------------------------------------------------------
// BN stats (block partials, no atomics) + finalize + normalize/relu
// ---------------------------------------------------------------------------
__global__ void bn_stats_kernel(const float* __restrict__ xs, float* __restrict__ part) {
    int c = threadIdx.x & 63, ry = threadIdx.x >> 6;   // blockDim = 256
    float s = 0.f, s2 = 0.f;
    for (int r = blockIdx.x * 4 + ry; r < N_NODES; r += gridDim.x * 4) {
        float v = xs[(size_t)r * 64 + c];
        s += v; s2 += v * v;
    }
    __shared__ float sh[256], sh2[256];
    sh[threadIdx.x] = s; sh2[threadIdx.x] = s2;
    __syncthreads();
    if (ry == 0) {
        s  = sh[c]  + sh[64 + c]  + sh[128 + c]  + sh[192 + c];
        s2 = sh2[c] + sh2[64 + c] + sh2[128 + c] + sh2[192 + c];
        part[blockIdx.x * 128 + c]      = s;
        part[blockIdx.x * 128 + 64 + c] = s2;
    }
}

__global__ void bn_finalize_kernel(const float* __restrict__ part, float* __restrict__ stats) {
    int c = threadIdx.x;   // 128 threads
    float s = 0.f;
    for (int b = 0; b < 256; b++) s += part[b * 128 + c];
    stats[c] = s;
}

__global__ void bn_norm_kernel(const float* __restrict__ xs, const float* __restrict__ stats,
                               const float* __restrict__ gamma, const float* __restrict__ beta,
                               float* __restrict__ out) {
    int i = blockIdx.x * blockDim.x + threadIdx.x;
    if (i >= NC) return;
    int c = i & 63;
    const float invN = 1.f / (float)N_NODES;
    float mu = stats[c] * invN;
    float var = stats[64 + c] * invN - mu * mu;
    float rs = rsqrtf(var + 1e-5f);
    float y = gamma[c] * (xs[i] - mu) * rs + beta[c];
    out[i] = fmaxf(y, 0.f);
}

// ---------------------------------------------------------------------------
// host
// ---------------------------------------------------------------------------
static void run_layer(const float* xin, const float* W, const float* as, const float* ad,
                      const float* b, const float* gm, const float* bt,
                      float* saved_out, float* final_out, float* S) {
    float* agg   = S + OFF_AGG;
    float* als   = S + OFF_ALS;
    float* ald   = S + OFF_ALD;
    float* stats = S + OFF_STATS;
    float* part  = S + OFF_PART;
    float* wa    = S + OFF_WA;
    int* deg     = (int*)(S + OFF_DEG);
    int* rowp    = (int*)(S + OFF_ROWP);
    int* csrc    = (int*)(S + OFF_CSRC);

    wa_kernel<<<1, 256>>>(W, as, ad, wa);
    al_kernel<<<(N_NODES + 255) / 256, 256>>>(xin, wa, als, ald);
    dst_kernel<<<(N_NODES * 32 + 255) / 256, 256>>>(rowp, deg, csrc, als, ald, xin, agg);
    gemm2_kernel<<<(N_NODES + G2_ROWS - 1) / G2_ROWS, 256, 99328>>>(agg, W, b, saved_out);
    bn_stats_kernel<<<256, 256>>>(saved_out, part);
    bn_finalize_kernel<<<1, 128>>>(part, stats);
    bn_norm_kernel<<<(NC + 255) / 256, 256>>>(saved_out, stats, gm, bt, final_out);
}

extern "C" void kernel_launch(void* const* d_in, const int* in_sizes, int n_in,
                              void* d_out, int out_size) {
    const float* x   = (const float*)d_in[0];
    const void*  ei  = d_in[1];
    const int*   ei32 = (const int*)d_in[1];
    const float* W0  = (const float*)d_in[3];
    const float* as0 = (const float*)d_in[4];
    const float* ad0 = (const float*)d_in[5];
    const float* b0  = (const float*)d_in[6];
    const float* g0  = (const float*)d_in[7];
    const float* bt0 = (const float*)d_in[8];
    const float* W1  = (const float*)d_in[9];
    const float* as1 = (const float*)d_in[10];
    const float* ad1 = (const float*)d_in[11];
    const float* b1  = (const float*)d_in[12];
    const float* g1  = (const float*)d_in[13];
    const float* bt1 = (const float*)d_in[14];

    void* sp = nullptr;
    cudaGetSymbolAddress(&sp, g_scratch);
    float* S = (float*)sp;
    int* deg  = (int*)(S + OFF_DEG);
    int* rowp = (int*)(S + OFF_ROWP);
    int* cur  = (int*)(S + OFF_CUR);
    int* csrc = (int*)(S + OFF_CSRC);

    cudaFuncSetAttribute(gemm2_kernel, cudaFuncAttributeMaxDynamicSharedMemorySize, 99328);

    // CSR build (once; identical for both layers)
    init_kernel<<<(N_NODES + 255) / 256, 256>>>(ei32, deg);
    hist_kernel<<<(E_TOT + 255) / 256, 256>>>(ei, deg);
    scan_kernel<<<1, SCAN_T>>>(deg, rowp, cur);
    scatter_kernel<<<(E_TOT + 255) / 256, 256>>>(ei, cur, csrc);

    float* out_final = (float*)d_out;
    float* out_saved = out_final + NC;

    // layer 1: saved -> out_saved (temp; overwritten by layer 2), BN out -> h1
    run_layer(x, W0, as0, ad0, b0, g0, bt0, out_saved, S + OFF_H1, S);
    // layer 2: input h1; saved -> out_saved; final -> out_final
    run_layer(S + OFF_H1, W1, as1, ad1, b1, g1, bt1, out_saved, out_final, S);
}

// round 10
// speedup vs baseline: 1.1309x; 1.0614x over previous
#include <cuda_runtime.h>
#include <math.h>

#define N_NODES 50000
#define N_EDGES 800000
#define E_TOT   850000          // + self loops
#define C       64
#define NC      (N_NODES * C)   // 3,200,000
#define NH      (N_NODES * 4)   // 200,000

// ---- scratch layout (floats; ints aliased) ----
#define OFF_AGG   0
#define SZ_AGG    (N_NODES * 256)          // 12,800,000
#define OFF_ALS   (OFF_AGG + SZ_AGG)
#define OFF_ALD   (OFF_ALS + NH)
#define OFF_H1    (OFF_ALD + NH)
#define OFF_STATS (OFF_H1 + NC)            // 256 (two layers x 128)
#define OFF_WA    (OFF_STATS + 256)        // 1024 (two layers x 512)
#define OFF_DEG   (OFF_WA + 1024)          // ints
#define OFF_ROWP  (OFF_DEG + N_NODES)
#define OFF_CUR   (OFF_ROWP + N_NODES)
#define OFF_CSRC  (OFF_CUR + N_NODES)
#define SCRATCH_TOTAL (OFF_CSRC + E_TOT)

__device__ __align__(16) float g_scratch[SCRATCH_TOTAL];
__device__ int g_is64;

__device__ __forceinline__ float lrelu(float x) { return x > 0.f ? x : 0.2f * x; }

__device__ __forceinline__ void edge_endpoints(const void* ei, int e, int& s, int& d) {
    if (e < N_EDGES) {
        if (g_is64) {
            const long long* p = (const long long*)ei;
            s = (int)p[e]; d = (int)p[N_EDGES + e];
        } else {
            const int* p = (const int*)ei;
            s = p[e]; d = p[N_EDGES + e];
        }
    } else {
        s = d = e - N_EDGES;
    }
}

// ---------------------------------------------------------------------------
// init: zero degree counters + detect edge dtype
// ---------------------------------------------------------------------------
__global__ void init_kernel(const int* __restrict__ ei32, int* __restrict__ deg) {
    int i = blockIdx.x * blockDim.x + threadIdx.x;
    if (i == 0) {
        int all0 = 1;
        #pragma unroll 8
        for (int k = 0; k < 64; k++) all0 &= (ei32[2 * k + 1] == 0);
        g_is64 = all0;
    }
    if (i < N_NODES) deg[i] = 0;
}

// ---------------------------------------------------------------------------
// hist: 2 edges per thread, vectorized dst loads
// ---------------------------------------------------------------------------
__global__ void hist_kernel(const void* __restrict__ ei, int* __restrict__ deg) {
    int t = blockIdx.x * blockDim.x + threadIdx.x;
    int e0 = t * 2;
    if (e0 >= E_TOT) return;
    if (e0 + 1 < N_EDGES) {
        int d0, d1;
        if (g_is64) {
            longlong2 dd = ((const longlong2*)((const long long*)ei + N_EDGES))[t];
            d0 = (int)dd.x; d1 = (int)dd.y;
        } else {
            int2 dd = ((const int2*)((const int*)ei + N_EDGES))[t];
            d0 = dd.x; d1 = dd.y;
        }
        atomicAdd(&deg[d0], 1);
        atomicAdd(&deg[d1], 1);
    } else {
        for (int e = e0; e < e0 + 2 && e < E_TOT; e++) {
            int s, d; edge_endpoints(ei, e, s, d); (void)s;
            atomicAdd(&deg[d], 1);
        }
    }
}

#define SCAN_T 1024
#define SCAN_CHUNK 49
__global__ __launch_bounds__(SCAN_T) void scan_kernel(const int* __restrict__ deg,
                                                      int* __restrict__ row_ptr,
                                                      int* __restrict__ cursor) {
    __shared__ int sm[SCAN_T];
    int t = threadIdx.x;
    int base = t * SCAN_CHUNK;
    int s = 0;
    for (int i = 0; i < SCAN_CHUNK; i++) {
        int idx = base + i;
        if (idx < N_NODES) s += deg[idx];
    }
    sm[t] = s;
    __syncthreads();
    for (int off = 1; off < SCAN_T; off <<= 1) {
        int v = 0;
        if (t >= off) v = sm[t - off];
        __syncthreads();
        if (t >= off) sm[t] += v;
        __syncthreads();
    }
    int ex = (t == 0) ? 0 : sm[t - 1];
    for (int i = 0; i < SCAN_CHUNK; i++) {
        int idx = base + i;
        if (idx < N_NODES) {
            row_ptr[idx] = ex;
            cursor[idx] = ex;
            ex += deg[idx];
        }
    }
}

// ---------------------------------------------------------------------------
// scatter: 2 edges per thread, vectorized loads
// ---------------------------------------------------------------------------
__global__ void scatter_kernel(const void* __restrict__ ei, int* __restrict__ cursor,
                               int* __restrict__ csr_src) {
    int t = blockIdx.x * blockDim.x + threadIdx.x;
    int e0 = t * 2;
    if (e0 >= E_TOT) return;
    if (e0 + 1 < N_EDGES) {
        int s0, s1, d0, d1;
        if (g_is64) {
            longlong2 ss = ((const longlong2*)((const long long*)ei))[t];
            longlong2 dd = ((const longlong2*)((const long long*)ei + N_EDGES))[t];
            s0 = (int)ss.x; s1 = (int)ss.y; d0 = (int)dd.x; d1 = (int)dd.y;
        } else {
            int2 ss = ((const int2*)((const int*)ei))[t];
            int2 dd = ((const int2*)((const int*)ei + N_EDGES))[t];
            s0 = ss.x; s1 = ss.y; d0 = dd.x; d1 = dd.y;
        }
        int p0 = atomicAdd(&cursor[d0], 1);
        int p1 = atomicAdd(&cursor[d1], 1);
        csr_src[p0] = s0;
        csr_src[p1] = s1;
    } else {
        for (int e = e0; e < e0 + 2 && e < E_TOT; e++) {
            int s, d; edge_endpoints(ei, e, s, d);
            int pos = atomicAdd(&cursor[d], 1);
            csr_src[pos] = s;
        }
    }
}

// ---------------------------------------------------------------------------
// wa precompute for BOTH layers (block per layer) + zero stats
// wa[l*512 + h*64+ci] = sum_c W[ci, h*64+c]*asrc[h,c]; +256 for adst
// ---------------------------------------------------------------------------
__global__ void wa_kernel(const float* __restrict__ W0, const float* __restrict__ as0,
                          const float* __restrict__ ad0,
                          const float* __restrict__ W1, const float* __restrict__ as1,
                          const float* __restrict__ ad1,
                          float* __restrict__ wa, float* __restrict__ stats) {
    int l = blockIdx.x;
    const float* W    = l ? W1 : W0;
    const float* asrc = l ? as1 : as0;
    const float* adst = l ? ad1 : ad0;
    int t = threadIdx.x;            // 256 threads
    int h = t >> 6, ci = t & 63;
    float s = 0.f, d = 0.f;
    #pragma unroll 8
    for (int c = 0; c < 64; c++) {
        float w = W[ci * 256 + h * 64 + c];
        s += w * asrc[h * 64 + c];
        d += w * adst[h * 64 + c];
    }
    wa[l * 512 + h * 64 + ci] = s;
    wa[l * 512 + 256 + h * 64 + ci] = d;
    if (t < 128) stats[l * 128 + t] = 0.f;
}

// ---------------------------------------------------------------------------
// attention logits, warp per node: lane owns channels (2l, 2l+1); coalesced
// ---------------------------------------------------------------------------
__global__ __launch_bounds__(256) void al_kernel(const float* __restrict__ x,
                                                 const float* __restrict__ wa,
                                                 float* __restrict__ als,
                                                 float* __restrict__ ald) {
    __shared__ float swa[512];
    for (int i = threadIdx.x; i < 512; i += 256) swa[i] = wa[i];
    __syncthreads();
    int w = (blockIdx.x * blockDim.x + threadIdx.x) >> 5;
    int lane = threadIdx.x & 31;
    if (w >= N_NODES) return;
    float2 v = ((const float2*)x)[(size_t)w * 32 + lane];
    float rs[4], rd[4];
    #pragma unroll
    for (int h = 0; h < 4; h++) {
        rs[h] = v.x * swa[h * 64 + 2 * lane] + v.y * swa[h * 64 + 2 * lane + 1];
        rd[h] = v.x * swa[256 + h * 64 + 2 * lane] + v.y * swa[256 + h * 64 + 2 * lane + 1];
    }
    #pragma unroll
    for (int o = 16; o; o >>= 1) {
        #pragma unroll
        for (int h = 0; h < 4; h++) {
            rs[h] += __shfl_xor_sync(0xffffffffu, rs[h], o);
            rd[h] += __shfl_xor_sync(0xffffffffu, rd[h], o);
        }
    }
    if (lane == 0) {
        *(float4*)(als + (size_t)w * 4) = make_float4(rs[0], rs[1], rs[2], rs[3]);
        *(float4*)(ald + (size_t)w * 4) = make_float4(rd[0], rd[1], rd[2], rd[3]);
    }
}

// ---------------------------------------------------------------------------
// SINGLE-PASS fused softmax + gather. Warp per dst node.
// Accumulate unnormalized p*x and den simultaneously; divide once at the end.
// ---------------------------------------------------------------------------
__global__ __launch_bounds__(256) void dst_kernel(const int* __restrict__ row_ptr,
                                                  const int* __restrict__ deg,
                                                  const int* __restrict__ csr_src,
                                                  const float* __restrict__ als,
                                                  const float* __restrict__ ald,
                                                  const float* __restrict__ x,
                                                  float* __restrict__ agg) {
    int w = (blockIdx.x * blockDim.x + threadIdx.x) >> 5;
    int lane = threadIdx.x & 31;
    if (w >= N_NODES) return;
    int start = row_ptr[w];
    int n = deg[w];
    float4 ad = *(const float4*)(ald + (size_t)w * 4);

    float4 dl = make_float4(0.f, 0.f, 0.f, 0.f);   // per-lane denominator partials
    float2 r0 = make_float2(0.f, 0.f), r1 = r0, r2 = r0, r3 = r0;

    for (int base = 0; base < n; base += 32) {
        int j = base + lane;
        int s = 0;
        float4 p = make_float4(0.f, 0.f, 0.f, 0.f);
        if (j < n) {
            s = csr_src[start + j];
            float4 a = *(const float4*)(als + (size_t)s * 4);
            p.x = __expf(lrelu(a.x + ad.x));
            p.y = __expf(lrelu(a.y + ad.y));
            p.z = __expf(lrelu(a.z + ad.z));
            p.w = __expf(lrelu(a.w + ad.w));
        }
        dl.x += p.x; dl.y += p.y; dl.z += p.z; dl.w += p.w;
        int cnt = n - base; if (cnt > 32) cnt = 32;
        for (int jj = 0; jj < cnt; jj++) {
            int ss   = __shfl_sync(0xffffffffu, s, jj);
            float a0 = __shfl_sync(0xffffffffu, p.x, jj);
            float a1 = __shfl_sync(0xffffffffu, p.y, jj);
            float a2 = __shfl_sync(0xffffffffu, p.z, jj);
            float a3 = __shfl_sync(0xffffffffu, p.w, jj);
            float2 v = *((const float2*)x + (size_t)ss * 32 + lane);
            r0.x += a0 * v.x; r0.y += a0 * v.y;
            r1.x += a1 * v.x; r1.y += a1 * v.y;
            r2.x += a2 * v.x; r2.y += a2 * v.y;
            r3.x += a3 * v.x; r3.y += a3 * v.y;
        }
    }
    // reduce denominator across warp
    #pragma unroll
    for (int o = 16; o; o >>= 1) {
        dl.x += __shfl_xor_sync(0xffffffffu, dl.x, o);
        dl.y += __shfl_xor_sync(0xffffffffu, dl.y, o);
        dl.z += __shfl_xor_sync(0xffffffffu, dl.z, o);
        dl.w += __shfl_xor_sync(0xffffffffu, dl.w, o);
    }
    float i0 = 1.0f / (dl.x + 1e-16f);
    float i1 = 1.0f / (dl.y + 1e-16f);
    float i2 = 1.0f / (dl.z + 1e-16f);
    float i3 = 1.0f / (dl.w + 1e-16f);
    float2* ag = (float2*)(agg + (size_t)w * 256);
    ag[lane]      = make_float2(r0.x * i0, r0.y * i0);
    ag[32 + lane] = make_float2(r1.x * i1, r1.y * i1);
    ag[64 + lane] = make_float2(r2.x * i2, r2.y * i2);
    ag[96 + lane] = make_float2(r3.x * i3, r3.y * i3);
}

// ---------------------------------------------------------------------------
// GEMM2 + fused BN stats: saved = 0.25*agg@Wcat + bias; stats += (sum, sumsq)
// ---------------------------------------------------------------------------
#define G2_ROWS 128
__global__ __launch_bounds__(256) void gemm2s_kernel(const float* __restrict__ agg,
                                                     const float* __restrict__ W,
                                                     const float* __restrict__ bias,
                                                     float* __restrict__ out,
                                                     float* __restrict__ stats) {
    extern __shared__ float sm[];
    float* sW = sm;              // 16384 floats
    float* sA = sm + 16384;      // 64*132 floats
    const float4* W4 = (const float4*)W;
    float4* sW4 = (float4*)sW;
    #pragma unroll 4
    for (int i = threadIdx.x; i < 4096; i += 256) sW4[i] = W4[i];

    int row0 = blockIdx.x * G2_ROWS;
    int cg = threadIdx.x & 15;    // 4 cols each -> 64 cols
    int rg = threadIdx.x >> 4;    // 8 rows each -> 128 rows
    float acc[8][4];
    #pragma unroll
    for (int r = 0; r < 8; r++) { acc[r][0] = acc[r][1] = acc[r][2] = acc[r][3] = 0.f; }

    for (int kc = 0; kc < 4; kc++) {
        __syncthreads();
        for (int i = threadIdx.x; i < 2048; i += 256) {
            int r = i >> 4, c4 = i & 15;
            float4 v = make_float4(0.f, 0.f, 0.f, 0.f);
            int row = row0 + r;
            if (row < N_NODES) v = *(const float4*)(agg + (size_t)row * 256 + kc * 64 + c4 * 4);
            sA[(c4 * 4 + 0) * 132 + r] = v.x;
            sA[(c4 * 4 + 1) * 132 + r] = v.y;
            sA[(c4 * 4 + 2) * 132 + r] = v.z;
            sA[(c4 * 4 + 3) * 132 + r] = v.w;
        }
        __syncthreads();
        const float* wbase = sW + kc * 64;
        #pragma unroll 4
        for (int k = 0; k < 64; k++) {
            float4 b4 = *(const float4*)(wbase + k * 256 + cg * 4);
            const float* arow = sA + k * 132 + rg * 8;
            float4 a0 = *(const float4*)(arow);
            float4 a1 = *(const float4*)(arow + 4);
            float av[8] = {a0.x, a0.y, a0.z, a0.w, a1.x, a1.y, a1.z, a1.w};
            #pragma unroll
            for (int r = 0; r < 8; r++) {
                acc[r][0] += av[r] * b4.x;
                acc[r][1] += av[r] * b4.y;
                acc[r][2] += av[r] * b4.z;
                acc[r][3] += av[r] * b4.w;
            }
        }
    }
    float4 bb = *((const float4*)bias + cg);
    float s1[4] = {0.f, 0.f, 0.f, 0.f}, s2[4] = {0.f, 0.f, 0.f, 0.f};
    #pragma unroll
    for (int r = 0; r < 8; r++) {
        int row = row0 + rg * 8 + r;
        if (row < N_NODES) {
            float o0 = 0.25f * acc[r][0] + bb.x;
            float o1 = 0.25f * acc[r][1] + bb.y;
            float o2 = 0.25f * acc[r][2] + bb.z;
            float o3 = 0.25f * acc[r][3] + bb.w;
            *(float4*)(out + (size_t)row * 64 + cg * 4) = make_float4(o0, o1, o2, o3);
            s1[0] += o0; s1[1] += o1; s1[2] += o2; s1[3] += o3;
            s2[0] += o0 * o0; s2[1] += o1 * o1; s2[2] += o2 * o2; s2[3] += o3 * o3;
        }
    }
    // block reduce: sA reused. layout: [rg][64] for sum, +1024 for sumsq
    __syncthreads();
    #pragma unroll
    for (int k = 0; k < 4; k++) {
        sA[rg * 64 + cg * 4 + k] = s1[k];
        sA[1024 + rg * 64 + cg * 4 + k] = s2[k];
    }
    __syncthreads();
    int t = threadIdx.x;
    if (t < 64) {
        float a = 0.f, b = 0.f;
        #pragma unroll
        for (int g = 0; g < 16; g++) {
            a += sA[g * 64 + t];
            b += sA[1024 + g * 64 + t];
        }
        atomicAdd(&stats[t], a);
        atomicAdd(&stats[64 + t], b);
    }
}

// ---------------------------------------------------------------------------
// BN normalize + relu (final layer output)
// ---------------------------------------------------------------------------
__global__ __launch_bounds__(256) void bn_norm_kernel(const float* __restrict__ xs,
                                                      const float* __restrict__ stats,
                                                      const float* __restrict__ gamma,
                                                      const float* __restrict__ beta,
                                                      float* __restrict__ out) {
    __shared__ float sc[64], sh[64];
    int t = threadIdx.x;
    if (t < 64) {
        const float invN = 1.f / (float)N_NODES;
        float mu = stats[t] * invN;
        float var = stats[64 + t] * invN - mu * mu;
        float rs = rsqrtf(var + 1e-5f);
        float g = gamma[t];
        sc[t] = g * rs;
        sh[t] = beta[t] - g * mu * rs;
    }
    __syncthreads();
    int i = blockIdx.x * blockDim.x + t;
    if (i >= NC) return;
    int c = i & 63;
    out[i] = fmaxf(fmaf(xs[i], sc[c], sh[c]), 0.f);
}

// ---------------------------------------------------------------------------
// Fused: BN normalize + relu (layer 1) AND layer-2 attention logits.
// Warp per node; lane owns channels (2l, 2l+1).
// ---------------------------------------------------------------------------
__global__ __launch_bounds__(256) void bn_norm_al_kernel(const float* __restrict__ xs,
                                                         const float* __restrict__ stats,
                                                         const float* __restrict__ gamma,
                                                         const float* __restrict__ beta,
                                                         const float* __restrict__ wa2,
                                                         float* __restrict__ h1,
                                                         float* __restrict__ als,
                                                         float* __restrict__ ald) {
    __shared__ float swa[512];
    __shared__ float sc[64], sh[64];
    int t = threadIdx.x;
    for (int i = t; i < 512; i += 256) swa[i] = wa2[i];
    if (t < 64) {
        const float invN = 1.f / (float)N_NODES;
        float mu = stats[t] * invN;
        float var = stats[64 + t] * invN - mu * mu;
        float rs = rsqrtf(var + 1e-5f);
        float g = gamma[t];
        sc[t] = g * rs;
        sh[t] = beta[t] - g * mu * rs;
    }
    __syncthreads();
    int w = (blockIdx.x * blockDim.x + t) >> 5;
    int lane = t & 31;
    if (w >= N_NODES) return;
    int c0 = 2 * lane, c1 = c0 + 1;
    float2 v = ((const float2*)xs)[(size_t)w * 32 + lane];
    float y0 = fmaxf(fmaf(v.x, sc[c0], sh[c0]), 0.f);
    float y1 = fmaxf(fmaf(v.y, sc[c1], sh[c1]), 0.f);
    ((float2*)h1)[(size_t)w * 32 + lane] = make_float2(y0, y1);
    float rs4[4], rd4[4];
    #pragma unroll
    for (int h = 0; h < 4; h++) {
        rs4[h] = y0 * swa[h * 64 + c0] + y1 * swa[h * 64 + c1];
        rd4[h] = y0 * swa[256 + h * 64 + c0] + y1 * swa[256 + h * 64 + c1];
    }
    #pragma unroll
    for (int o = 16; o; o >>= 1) {
        #pragma unroll
        for (int h = 0; h < 4; h++) {
            rs4[h] += __shfl_xor_sync(0xffffffffu, rs4[h], o);
            rd4[h] += __shfl_xor_sync(0xffffffffu, rd4[h], o);
        }
    }
    if (lane == 0) {
        *(float4*)(als + (size_t)w * 4) = make_float4(rs4[0], rs4[1], rs4[2], rs4[3]);
        *(float4*)(ald + (size_t)w * 4) = make_float4(rd4[0], rd4[1], rd4[2], rd4[3]);
    }
}

// ---------------------------------------------------------------------------
// host
// ---------------------------------------------------------------------------
extern "C" void kernel_launch(void* const* d_in, const int* in_sizes, int n_in,
                              void* d_out, int out_size) {
    const float* x   = (const float*)d_in[0];
    const void*  ei  = d_in[1];
    const int*   ei32 = (const int*)d_in[1];
    const float* W0  = (const float*)d_in[3];
    const float* as0 = (const float*)d_in[4];
    const float* ad0 = (const float*)d_in[5];
    const float* b0  = (const float*)d_in[6];
    const float* g0  = (const float*)d_in[7];
    const float* bt0 = (const float*)d_in[8];
    const float* W1  = (const float*)d_in[9];
    const float* as1 = (const float*)d_in[10];
    const float* ad1 = (const float*)d_in[11];
    const float* b1  = (const float*)d_in[12];
    const float* g1  = (const float*)d_in[13];
    const float* bt1 = (const float*)d_in[14];

    void* sp = nullptr;
    cudaGetSymbolAddress(&sp, g_scratch);
    float* S = (float*)sp;
    float* agg    = S + OFF_AGG;
    float* als    = S + OFF_ALS;
    float* ald    = S + OFF_ALD;
    float* h1     = S + OFF_H1;
    float* stats  = S + OFF_STATS;   // [0:128) layer1, [128:256) layer2
    float* wa     = S + OFF_WA;      // [0:512) layer1, [512:1024) layer2
    int* deg  = (int*)(S + OFF_DEG);
    int* rowp = (int*)(S + OFF_ROWP);
    int* cur  = (int*)(S + OFF_CUR);
    int* csrc = (int*)(S + OFF_CSRC);

    cudaFuncSetAttribute(gemm2s_kernel, cudaFuncAttributeMaxDynamicSharedMemorySize, 99328);

    float* out_final = (float*)d_out;
    float* out_saved = out_final + NC;

    const int NWARP_GRID = (N_NODES * 32 + 255) / 256;

    // ---- CSR build (once) ----
    init_kernel<<<(N_NODES + 255) / 256, 256>>>(ei32, deg);
    hist_kernel<<<(E_TOT / 2 + 255) / 256, 256>>>(ei, deg);
    scan_kernel<<<1, SCAN_T>>>(deg, rowp, cur);
    scatter_kernel<<<(E_TOT / 2 + 255) / 256, 256>>>(ei, cur, csrc);

    // ---- both layers' wa + zero stats ----
    wa_kernel<<<2, 256>>>(W0, as0, ad0, W1, as1, ad1, wa, stats);

    // ---- layer 1 ----
    al_kernel<<<NWARP_GRID, 256>>>(x, wa, als, ald);
    dst_kernel<<<NWARP_GRID, 256>>>(rowp, deg, csrc, als, ald, x, agg);
    gemm2s_kernel<<<(N_NODES + G2_ROWS - 1) / G2_ROWS, 256, 99328>>>(agg, W0, b0, out_saved, stats);
    // BN(layer1) + ReLU -> h1, fused with layer-2 logits
    bn_norm_al_kernel<<<NWARP_GRID, 256>>>(out_saved, stats, g0, bt0, wa + 512, h1, als, ald);

    // ---- layer 2 ----
    dst_kernel<<<NWARP_GRID, 256>>>(rowp, deg, csrc, als, ald, h1, agg);
    gemm2s_kernel<<<(N_NODES + G2_ROWS - 1) / G2_ROWS, 256, 99328>>>(agg, W1, b1, out_saved, stats + 128);
    bn_norm_kernel<<<(NC + 255) / 256, 256>>>(out_saved, stats + 128, g1, bt1, out_final);
}